// round 2
// baseline (speedup 1.0000x reference)
#include <cuda_runtime.h>

#define DH 64
#define DIN 128
#define MAXN 100000
#define MAXE 1000000
#define EPSN 1e-5f
#define SLOPE 0.2f

// ---------------- device scratch (no allocations allowed) ----------------
__device__ float g_h[MAXN * DH];     // current node features
__device__ float g_xw[MAXN * DH];    // h @ W  (gather source)
__device__ float g_agg[MAXN * DH];   // aggregation buffer (init = xw*dinv^2 + b)
__device__ float g_deg[MAXN];
__device__ float g_dinv[MAXN];
__device__ double g_sum1[DH], g_sq1[DH], g_sum2[DH], g_sq2[DH];
__device__ float g_A[DH], g_B[DH];   // folded GraphNorm affine

// ---------------- small utility kernels ----------------
__global__ void zero_kernel(int n) {
    int i = blockIdx.x * blockDim.x + threadIdx.x;
    if (i < n) g_deg[i] = 0.f;
    if (i < DH) {
        g_sum1[i] = 0.0; g_sq1[i] = 0.0;
        g_sum2[i] = 0.0; g_sq2[i] = 0.0;
    }
}

__global__ void deg_kernel(const int* __restrict__ dst, int E) {
    int e = blockIdx.x * blockDim.x + threadIdx.x;
    if (e < E) atomicAdd(&g_deg[dst[e]], 1.0f);
}

__global__ void dinv_kernel(int n) {
    int i = blockIdx.x * blockDim.x + threadIdx.x;
    if (i < n) g_dinv[i] = rsqrtf(g_deg[i] + 1.0f);
}

// ---------------- GEMM: out[n,64] = X[n,K] @ W[K,64] ----------------
// LAYER=false: X = external input, writes g_h = XW + bias
// LAYER=true : X = g_h, writes g_xw = XW and g_agg = XW*dinv^2 + bias
template<int K, int ROWS, bool LAYER>
__global__ void __launch_bounds__(256)
gemm_kernel(const float* __restrict__ Xext, const float* __restrict__ W,
            const float* __restrict__ bias, int n) {
    constexpr int CPT = ROWS / 4;      // cols per thread (ROWS*64/256)
    constexpr int TPR = DH / CPT;      // threads per row
    __shared__ float sW[K * DH];
    __shared__ float sX[ROWS * (K + 4)];

    const float* X = LAYER ? g_h : Xext;
    const int tid = threadIdx.x;
    const int row0 = blockIdx.x * ROWS;

    for (int i = tid * 4; i < K * DH; i += 1024)
        *(float4*)(sW + i) = *(const float4*)(W + i);
    for (int i = tid * 4; i < ROWS * K; i += 1024) {
        int r = i / K, k = i - r * K;
        int gr = row0 + r;
        float4 v = make_float4(0.f, 0.f, 0.f, 0.f);
        if (gr < n) v = *(const float4*)(X + (size_t)gr * K + k);
        *(float4*)(sX + r * (K + 4) + k) = v;
    }
    __syncthreads();

    const int r = tid / TPR;
    const int c0 = (tid % TPR) * CPT;
    float acc[CPT];
#pragma unroll
    for (int j = 0; j < CPT; j++) acc[j] = 0.f;

#pragma unroll 4
    for (int k = 0; k < K; k++) {
        float hv = sX[r * (K + 4) + k];
        const float4* wp = (const float4*)(sW + k * DH + c0);
#pragma unroll
        for (int jj = 0; jj < CPT / 4; jj++) {
            float4 w = wp[jj];
            acc[jj * 4 + 0] += hv * w.x;
            acc[jj * 4 + 1] += hv * w.y;
            acc[jj * 4 + 2] += hv * w.z;
            acc[jj * 4 + 3] += hv * w.w;
        }
    }

    int gr = row0 + r;
    if (gr < n) {
        if (!LAYER) {
#pragma unroll
            for (int j = 0; j < CPT; j++)
                g_h[(size_t)gr * DH + c0 + j] = acc[j] + bias[c0 + j];
        } else {
            float d = g_dinv[gr];
            float d2 = d * d;
#pragma unroll
            for (int j = 0; j < CPT; j++) {
                float v = acc[j];
                g_xw[(size_t)gr * DH + c0 + j] = v;
                g_agg[(size_t)gr * DH + c0 + j] = v * d2 + bias[c0 + j];
            }
        }
    }
}

// ---------------- edge scatter: agg[dst] += coef * xw[src] ----------------
// 16 lanes per edge, one float4 per lane; vector red (sm_90+) for 4x fewer atomics.
__global__ void __launch_bounds__(256)
scatter_kernel(const int* __restrict__ src, const int* __restrict__ dst, int E) {
    int tid = threadIdx.x;
    int lane = tid & 31;
    int gw = (blockIdx.x * 256 + tid) >> 5;
    int e = gw * 2 + (lane >> 4);
    if (e >= E) return;
    int s = src[e], d = dst[e];
    float c = g_dinv[s] * g_dinv[d];
    int q = (lane & 15) * 4;
    float4 v = *(const float4*)&g_xw[(size_t)s * DH + q];
    float* p = &g_agg[(size_t)d * DH + q];
    asm volatile("red.global.add.v4.f32 [%0], {%1,%2,%3,%4};"
                 :: "l"(p), "f"(v.x * c), "f"(v.y * c), "f"(v.z * c), "f"(v.w * c)
                 : "memory");
}

// ---------------- per-feature sum / sumsq reduction over nodes ----------------
template<int L>
__global__ void __launch_bounds__(256)
stats_kernel(int n) {
    int j = threadIdx.x & 63;
    int slot = threadIdx.x >> 6;                  // 0..3
    int r = blockIdx.x * 4 + slot;
    int stride = gridDim.x * 4;
    float s = 0.f, q = 0.f;
    for (; r < n; r += stride) {
        float v = g_agg[(size_t)r * DH + j];
        s += v;
        q += v * v;
    }
    __shared__ float ss[4][DH];
    __shared__ float sq[4][DH];
    ss[slot][j] = s;
    sq[slot][j] = q;
    __syncthreads();
    if (threadIdx.x < DH) {
        double S = (double)ss[0][j] + ss[1][j] + ss[2][j] + ss[3][j];
        double Q = (double)sq[0][j] + sq[1][j] + sq[2][j] + sq[3][j];
        if (L == 1) { atomicAdd(&g_sum1[j], S); atomicAdd(&g_sq1[j], Q); }
        else        { atomicAdd(&g_sum2[j], S); atomicAdd(&g_sq2[j], Q); }
    }
}

// ---------------- fold GraphNorm into out = A*x + B ----------------
template<int L>
__global__ void finalize_kernel(const float* __restrict__ alpha,
                                const float* __restrict__ gamma,
                                const float* __restrict__ beta, int n) {
    int j = threadIdx.x;
    if (j >= DH) return;
    double S = (L == 1) ? g_sum1[j] : g_sum2[j];
    double Q = (L == 1) ? g_sq1[j] : g_sq2[j];
    double m = S / (double)n;
    double a = (double)alpha[j];
    // var = E[(x - a*m)^2] = E[x^2] - 2*a*m*E[x] + a^2*m^2
    double var = Q / (double)n - 2.0 * a * m * m + a * a * m * m;
    float inv = rsqrtf((float)var + EPSN);
    float g = gamma[j] * inv;
    g_A[j] = g;
    g_B[j] = beta[j] - g * (float)(a * m);
}

// LAYER1=true: apply LeakyReLU, write g_h.  false: write external out.
template<bool LAYER1>
__global__ void __launch_bounds__(256)
norm_kernel(float* __restrict__ out, int total) {
    int i = blockIdx.x * 256 + threadIdx.x;
    if (i >= total) return;
    int j = i & 63;
    float v = g_A[j] * g_agg[i] + g_B[j];
    if (LAYER1) {
        v = v > 0.f ? v : SLOPE * v;
        g_h[i] = v;
    } else {
        out[i] = v;
    }
}

// ---------------- launcher ----------------
extern "C" void kernel_launch(void* const* d_in, const int* in_sizes, int n_in,
                              void* d_out, int out_size) {
    const float* x    = (const float*)d_in[0];
    const int*   ei   = (const int*)d_in[1];
    const float* W_in = (const float*)d_in[2];
    const float* b_in = (const float*)d_in[3];
    const float* W1   = (const float*)d_in[4];
    const float* b1   = (const float*)d_in[5];
    const float* a1   = (const float*)d_in[6];
    const float* gm1  = (const float*)d_in[7];
    const float* be1  = (const float*)d_in[8];
    const float* W2   = (const float*)d_in[9];
    const float* b2   = (const float*)d_in[10];
    const float* a2   = (const float*)d_in[11];
    const float* gm2  = (const float*)d_in[12];
    const float* be2  = (const float*)d_in[13];
    float* out = (float*)d_out;

    const int n = in_sizes[0] / DIN;
    const int E = in_sizes[1] / 2;
    const int* src = ei;
    const int* dst = ei + E;
    const int total = n * DH;

    zero_kernel<<<(n + 255) / 256, 256>>>(n);
    deg_kernel<<<(E + 255) / 256, 256>>>(dst, E);
    dinv_kernel<<<(n + 255) / 256, 256>>>(n);

    // input projection: g_h = x @ W_in + b_in
    gemm_kernel<DIN, 16, false><<<(n + 15) / 16, 256>>>(x, W_in, b_in, n);

    // ---- layer 1 ----
    gemm_kernel<DH, 32, true><<<(n + 31) / 32, 256>>>(nullptr, W1, b1, n);
    scatter_kernel<<<(E + 15) / 16, 256>>>(src, dst, E);
    stats_kernel<1><<<1184, 256>>>(n);
    finalize_kernel<1><<<1, 64>>>(a1, gm1, be1, n);
    norm_kernel<true><<<(total + 255) / 256, 256>>>(nullptr, total);

    // ---- layer 2 ----
    gemm_kernel<DH, 32, true><<<(n + 31) / 32, 256>>>(nullptr, W2, b2, n);
    scatter_kernel<<<(E + 15) / 16, 256>>>(src, dst, E);
    stats_kernel<2><<<1184, 256>>>(n);
    finalize_kernel<2><<<1, 64>>>(a2, gm2, be2, n);
    norm_kernel<false><<<(total + 255) / 256, 256>>>(out, total);
}

// round 3
// speedup vs baseline: 1.6092x; 1.6092x over previous
#include <cuda_runtime.h>

#define DH 64
#define DIN 128
#define MAXN 100000
#define MAXE 1000000
#define EPSN 1e-5f
#define SLOPE 0.2f
typedef unsigned long long ull;

// ---------------- device scratch (no allocations allowed) ----------------
__device__ float g_h[MAXN * DH];     // proj output / layer input
__device__ float g_xw[MAXN * DH];    // h @ W (gather source)
__device__ float g_agg[MAXN * DH];   // aggregated output per layer
__device__ int   g_degi[MAXN];
__device__ int   g_cur[MAXN];
__device__ int   g_off[MAXN];        // exclusive offset within 1024-block
__device__ int   g_bsum[256];        // per-block sums -> exclusive scanned
__device__ float g_dinv[MAXN];
__device__ int   g_ssrc[MAXE];       // edge src sorted by dst
__device__ float g_scoef[MAXE];      // dinv[s]*dinv[d] sorted by dst
__device__ double g_sum1[DH], g_sq1[DH], g_sum2[DH], g_sq2[DH];
__device__ float g_A[DH], g_B[DH];   // folded GraphNorm affine

// ---------------- packed f32x2 helpers (sm_103a FFMA2 path) ----------------
#define FMA2(d,a,b) asm("fma.rn.f32x2 %0, %1, %2, %0;" : "+l"(d) : "l"(a), "l"(b))
#define PACK2(d,x)  asm("mov.b64 %0, {%1, %1};" : "=l"(d) : "f"(x))
#define ADD2(d,a,b) asm("add.rn.f32x2 %0, %1, %2;" : "=l"(d) : "l"(a), "l"(b))

// ---------------- small utility kernels ----------------
__global__ void zero_kernel(int n) {
    int i = blockIdx.x * blockDim.x + threadIdx.x;
    if (i < n) { g_degi[i] = 0; g_cur[i] = 0; }
    if (i < DH) {
        g_sum1[i] = 0.0; g_sq1[i] = 0.0;
        g_sum2[i] = 0.0; g_sq2[i] = 0.0;
    }
}

__global__ void deg_kernel(const int* __restrict__ dst, int E) {
    int e = blockIdx.x * blockDim.x + threadIdx.x;
    if (e < E) atomicAdd(&g_degi[dst[e]], 1);
}

__global__ void dinv_kernel(int n) {
    int i = blockIdx.x * blockDim.x + threadIdx.x;
    if (i < n) g_dinv[i] = rsqrtf((float)g_degi[i] + 1.0f);
}

// block-level inclusive scan -> exclusive offsets + block sums
__global__ void __launch_bounds__(1024) scan1_kernel(int n) {
    __shared__ int s[1024];
    int t = threadIdx.x;
    int i = blockIdx.x * 1024 + t;
    int v = (i < n) ? g_degi[i] : 0;
    s[t] = v; __syncthreads();
#pragma unroll
    for (int off = 1; off < 1024; off <<= 1) {
        int tmp = (t >= off) ? s[t - off] : 0;
        __syncthreads();
        s[t] += tmp;
        __syncthreads();
    }
    if (i < n) g_off[i] = s[t] - v;
    if (t == 1023) g_bsum[blockIdx.x] = s[1023];
}

__global__ void __launch_bounds__(256) scan2_kernel(int nb) {
    __shared__ int s[256];
    int t = threadIdx.x;
    int v = (t < nb) ? g_bsum[t] : 0;
    s[t] = v; __syncthreads();
#pragma unroll
    for (int off = 1; off < 256; off <<= 1) {
        int tmp = (t >= off) ? s[t - off] : 0;
        __syncthreads();
        s[t] += tmp;
        __syncthreads();
    }
    if (t < nb) g_bsum[t] = s[t] - v;
}

__global__ void __launch_bounds__(256) fill_kernel(const int* __restrict__ src,
                                                   const int* __restrict__ dst, int E) {
    int e = blockIdx.x * blockDim.x + threadIdx.x;
    if (e >= E) return;
    int d = dst[e], s = src[e];
    int p = g_off[d] + g_bsum[d >> 10] + atomicAdd(&g_cur[d], 1);
    g_ssrc[p] = s;
    g_scoef[p] = g_dinv[s] * g_dinv[d];
}

// ---------------- GEMM: out[n,64] = X[n,K] @ W[K,64] ----------------
// MODE 0: X = external input, out = g_h = XW + bias
// MODE 1: X = g_h (plain),    out = g_xw = XW
// MODE 2: X = norm(g_agg)+leaky (GraphNorm folded A,B), out = g_xw = XW
// 256 threads, 128 rows/block, per-thread 4 rows x 8 cols via FFMA2.
template<int K, int MODE>
__global__ void __launch_bounds__(256)
gemm_kernel(const float* __restrict__ Xext, const float* __restrict__ W,
            const float* __restrict__ bias, int n) {
    constexpr int S = K + 2;          // pad: 4*S % 32 == 8 -> conflict-free rg banks
    constexpr int BR = 128;
    constexpr int KQ = K / 4;
    extern __shared__ float sm[];
    float* sW = sm;                   // K*64
    float* sX = sm + K * DH;          // BR*S

    const int tid = threadIdx.x;
    const int row0 = blockIdx.x * BR;
    const float* X = (MODE == 0) ? Xext : (MODE == 1 ? g_h : g_agg);

    for (int i = tid * 4; i < K * DH; i += 1024)
        *(float4*)(sW + i) = *(const float4*)(W + i);

    for (int i = tid; i < BR * KQ; i += 256) {
        int r = i / KQ, kq = (i - r * KQ) * 4;
        int gr = row0 + r;
        float4 v = make_float4(0.f, 0.f, 0.f, 0.f);
        if (gr < n) {
            v = *(const float4*)(X + (size_t)gr * K + kq);
            if (MODE == 2) {
                v.x = g_A[kq + 0] * v.x + g_B[kq + 0];
                v.y = g_A[kq + 1] * v.y + g_B[kq + 1];
                v.z = g_A[kq + 2] * v.z + g_B[kq + 2];
                v.w = g_A[kq + 3] * v.w + g_B[kq + 3];
                v.x = v.x > 0.f ? v.x : SLOPE * v.x;
                v.y = v.y > 0.f ? v.y : SLOPE * v.y;
                v.z = v.z > 0.f ? v.z : SLOPE * v.z;
                v.w = v.w > 0.f ? v.w : SLOPE * v.w;
            }
        }
        float* p = sX + r * S + kq;
        p[0] = v.x; p[1] = v.y; p[2] = v.z; p[3] = v.w;
    }
    __syncthreads();

    const int cg = tid & 7, rg = tid >> 3;
    const int c0 = cg * 8, r0 = rg * 4;
    ull acc[4][4];
#pragma unroll
    for (int i = 0; i < 4; i++)
#pragma unroll
        for (int j = 0; j < 4; j++) acc[i][j] = 0ull;

    const float* xp = sX + r0 * S;
    const float* wp = sW + c0;

#pragma unroll 4
    for (int k = 0; k < K; k++) {
        ull X0, X1, X2, X3;
        PACK2(X0, xp[k]);
        PACK2(X1, xp[S + k]);
        PACK2(X2, xp[2 * S + k]);
        PACK2(X3, xp[3 * S + k]);
        ulonglong2 wa = *(const ulonglong2*)(wp + (size_t)k * DH);
        ulonglong2 wb = *(const ulonglong2*)(wp + (size_t)k * DH + 4);
        FMA2(acc[0][0], X0, wa.x); FMA2(acc[0][1], X0, wa.y);
        FMA2(acc[0][2], X0, wb.x); FMA2(acc[0][3], X0, wb.y);
        FMA2(acc[1][0], X1, wa.x); FMA2(acc[1][1], X1, wa.y);
        FMA2(acc[1][2], X1, wb.x); FMA2(acc[1][3], X1, wb.y);
        FMA2(acc[2][0], X2, wa.x); FMA2(acc[2][1], X2, wa.y);
        FMA2(acc[2][2], X2, wb.x); FMA2(acc[2][3], X2, wb.y);
        FMA2(acc[3][0], X3, wa.x); FMA2(acc[3][1], X3, wa.y);
        FMA2(acc[3][2], X3, wb.x); FMA2(acc[3][3], X3, wb.y);
    }

    if (MODE == 0) {
        ulonglong2 ba = *(const ulonglong2*)(bias + c0);
        ulonglong2 bb = *(const ulonglong2*)(bias + c0 + 4);
#pragma unroll
        for (int i = 0; i < 4; i++) {
            int gr = row0 + r0 + i;
            if (gr < n) {
                ull o0, o1, o2, o3;
                ADD2(o0, acc[i][0], ba.x); ADD2(o1, acc[i][1], ba.y);
                ADD2(o2, acc[i][2], bb.x); ADD2(o3, acc[i][3], bb.y);
                ulonglong2* dp = (ulonglong2*)&g_h[(size_t)gr * DH + c0];
                dp[0] = make_ulonglong2(o0, o1);
                dp[1] = make_ulonglong2(o2, o3);
            }
        }
    } else {
#pragma unroll
        for (int i = 0; i < 4; i++) {
            int gr = row0 + r0 + i;
            if (gr < n) {
                ulonglong2* dp = (ulonglong2*)&g_xw[(size_t)gr * DH + c0];
                dp[0] = make_ulonglong2(acc[i][0], acc[i][1]);
                dp[1] = make_ulonglong2(acc[i][2], acc[i][3]);
            }
        }
    }
}

// ---------------- CSR gather aggregation: one warp per node ----------------
// agg[i] = sum_{e in in(i)} coef[e]*xw[src[e]] + dinv[i]^2*xw[i] + bias
__global__ void __launch_bounds__(256)
agg_kernel(const float* __restrict__ bias, int n) {
    int w = (blockIdx.x * 256 + threadIdx.x) >> 5;
    if (w >= n) return;
    int lane = threadIdx.x & 31;
    int half = lane >> 4;
    int q = (lane & 15) << 2;
    int start = g_off[w] + g_bsum[w >> 10];
    int end = start + g_degi[w];
    float4 a = make_float4(0.f, 0.f, 0.f, 0.f);
    for (int e = start + half; e < end; e += 2) {
        int s = g_ssrc[e];
        float c = g_scoef[e];
        float4 v = *(const float4*)&g_xw[(size_t)s * DH + q];
        a.x += c * v.x; a.y += c * v.y; a.z += c * v.z; a.w += c * v.w;
    }
    a.x += __shfl_xor_sync(0xffffffffu, a.x, 16);
    a.y += __shfl_xor_sync(0xffffffffu, a.y, 16);
    a.z += __shfl_xor_sync(0xffffffffu, a.z, 16);
    a.w += __shfl_xor_sync(0xffffffffu, a.w, 16);
    if (half == 0) {
        float d = g_dinv[w];
        float d2 = d * d;
        float4 xv = *(const float4*)&g_xw[(size_t)w * DH + q];
        float4 b = *(const float4*)&bias[q];
        float4 o;
        o.x = a.x + d2 * xv.x + b.x;
        o.y = a.y + d2 * xv.y + b.y;
        o.z = a.z + d2 * xv.z + b.z;
        o.w = a.w + d2 * xv.w + b.w;
        *(float4*)&g_agg[(size_t)w * DH + q] = o;
    }
}

// ---------------- per-feature sum / sumsq reduction over nodes ----------------
template<int L>
__global__ void __launch_bounds__(256)
stats_kernel(int n) {
    int j = threadIdx.x & 63;
    int slot = threadIdx.x >> 6;
    int r = blockIdx.x * 4 + slot;
    int stride = gridDim.x * 4;
    float s = 0.f, q = 0.f;
    for (; r < n; r += stride) {
        float v = g_agg[(size_t)r * DH + j];
        s += v;
        q += v * v;
    }
    __shared__ float ss[4][DH];
    __shared__ float sq[4][DH];
    ss[slot][j] = s;
    sq[slot][j] = q;
    __syncthreads();
    if (threadIdx.x < DH) {
        double S = (double)ss[0][j] + ss[1][j] + ss[2][j] + ss[3][j];
        double Q = (double)sq[0][j] + sq[1][j] + sq[2][j] + sq[3][j];
        if (L == 1) { atomicAdd(&g_sum1[j], S); atomicAdd(&g_sq1[j], Q); }
        else        { atomicAdd(&g_sum2[j], S); atomicAdd(&g_sq2[j], Q); }
    }
}

template<int L>
__global__ void finalize_kernel(const float* __restrict__ alpha,
                                const float* __restrict__ gamma,
                                const float* __restrict__ beta, int n) {
    int j = threadIdx.x;
    if (j >= DH) return;
    double S = (L == 1) ? g_sum1[j] : g_sum2[j];
    double Q = (L == 1) ? g_sq1[j] : g_sq2[j];
    double m = S / (double)n;
    double a = (double)alpha[j];
    double var = Q / (double)n - 2.0 * a * m * m + a * a * m * m;
    float inv = rsqrtf((float)var + EPSN);
    float g = gamma[j] * inv;
    g_A[j] = g;
    g_B[j] = beta[j] - g * (float)(a * m);
}

// final output: out = A*agg + B
__global__ void __launch_bounds__(256)
norm_out_kernel(float* __restrict__ out, int total) {
    int i = blockIdx.x * 256 + threadIdx.x;
    if (i >= total) return;
    int j = i & 63;
    out[i] = g_A[j] * g_agg[i] + g_B[j];
}

// ---------------- launcher ----------------
extern "C" void kernel_launch(void* const* d_in, const int* in_sizes, int n_in,
                              void* d_out, int out_size) {
    const float* x    = (const float*)d_in[0];
    const int*   ei   = (const int*)d_in[1];
    const float* W_in = (const float*)d_in[2];
    const float* b_in = (const float*)d_in[3];
    const float* W1   = (const float*)d_in[4];
    const float* b1   = (const float*)d_in[5];
    const float* a1   = (const float*)d_in[6];
    const float* gm1  = (const float*)d_in[7];
    const float* be1  = (const float*)d_in[8];
    const float* W2   = (const float*)d_in[9];
    const float* b2   = (const float*)d_in[10];
    const float* a2   = (const float*)d_in[11];
    const float* gm2  = (const float*)d_in[12];
    const float* be2  = (const float*)d_in[13];
    float* out = (float*)d_out;

    const int n = in_sizes[0] / DIN;
    const int E = in_sizes[1] / 2;
    const int* src = ei;
    const int* dst = ei + E;
    const int total = n * DH;
    const int nb = (n + 1023) >> 10;

    const int smemP = (DIN * DH + 128 * (DIN + 2)) * 4;  // 99328
    const int smemL = (DH * DH + 128 * (DH + 2)) * 4;    // 50176
    cudaFuncSetAttribute(gemm_kernel<DIN, 0>, cudaFuncAttributeMaxDynamicSharedMemorySize, smemP);
    cudaFuncSetAttribute(gemm_kernel<DH, 1>,  cudaFuncAttributeMaxDynamicSharedMemorySize, smemL);
    cudaFuncSetAttribute(gemm_kernel<DH, 2>,  cudaFuncAttributeMaxDynamicSharedMemorySize, smemL);

    const int gemm_blocks = (n + 127) / 128;

    // graph preprocessing (shared by both layers)
    zero_kernel<<<(n + 255) / 256, 256>>>(n);
    deg_kernel<<<(E + 255) / 256, 256>>>(dst, E);
    dinv_kernel<<<(n + 255) / 256, 256>>>(n);
    scan1_kernel<<<nb, 1024>>>(n);
    scan2_kernel<<<1, 256>>>(nb);
    fill_kernel<<<(E + 255) / 256, 256>>>(src, dst, E);

    // input projection: g_h = x @ W_in + b_in
    gemm_kernel<DIN, 0><<<gemm_blocks, 256, smemP>>>(x, W_in, b_in, n);

    // ---- layer 1 ----
    gemm_kernel<DH, 1><<<gemm_blocks, 256, smemL>>>(nullptr, W1, nullptr, n);
    agg_kernel<<<(n + 7) / 8, 256>>>(b1, n);
    stats_kernel<1><<<1184, 256>>>(n);
    finalize_kernel<1><<<1, 64>>>(a1, gm1, be1, n);

    // ---- layer 2 (GraphNorm1 + LeakyReLU fused into gemm input load) ----
    gemm_kernel<DH, 2><<<gemm_blocks, 256, smemL>>>(nullptr, W2, nullptr, n);
    agg_kernel<<<(n + 7) / 8, 256>>>(b2, n);
    stats_kernel<2><<<1184, 256>>>(n);
    finalize_kernel<2><<<1, 64>>>(a2, gm2, be2, n);
    norm_out_kernel<<<(total + 255) / 256, 256>>>(out, total);
}

// round 4
// speedup vs baseline: 1.7819x; 1.1073x over previous
#include <cuda_runtime.h>

#define DH 64
#define DIN 128
#define MAXN 100000
#define MAXE 1000000
#define EPSN 1e-5f
#define SLOPE 0.2f
typedef unsigned long long ull;

// ---------------- device scratch (no allocations allowed) ----------------
__device__ float g_xw[MAXN * DH];    // h @ W (gather source)
__device__ float g_agg[MAXN * DH];   // aggregated output per layer
__device__ int   g_degi[MAXN];
__device__ int   g_cur[MAXN];
__device__ int   g_off[MAXN];        // exclusive offset within 1024-block
__device__ int   g_bsum[256];        // per-block sums -> exclusive scanned
__device__ float g_dinv[MAXN];
__device__ int   g_ssrc[MAXE];       // edge src sorted by dst
__device__ float g_scoef[MAXE];      // dinv[s]*dinv[d] sorted by dst
__device__ double g_sum1[DH], g_sq1[DH], g_sum2[DH], g_sq2[DH];
__device__ float g_A[DH], g_B[DH];   // folded GraphNorm affine
__device__ float g_Wc[DIN * DH];     // W_in @ W1 (proj folded into layer1)
__device__ float g_bc[DH];           // b_in @ W1

// ---------------- packed f32x2 helpers (sm_103a FFMA2 path) ----------------
#define FMA2(d,a,b) asm("fma.rn.f32x2 %0, %1, %2, %0;" : "+l"(d) : "l"(a), "l"(b))
#define PACK2(d,x)  asm("mov.b64 %0, {%1, %1};" : "=l"(d) : "f"(x))
#define ADD2(d,a,b) asm("add.rn.f32x2 %0, %1, %2;" : "=l"(d) : "l"(a), "l"(b))

// ---------------- combined weight: Wc = W_in @ W1, bc = b_in @ W1 ----------------
__global__ void __launch_bounds__(256)
wc_kernel(const float* __restrict__ Win, const float* __restrict__ W1,
          const float* __restrict__ b_in) {
    __shared__ float sW1[DH * DH];
    int t = threadIdx.x;
    for (int i = t; i < DH * DH; i += 256) sW1[i] = W1[i];
    __syncthreads();
    int o = blockIdx.x * 256 + t;            // 8192 outputs
    int i = o >> 6, j = o & 63;
    float s = 0.f;
#pragma unroll 16
    for (int k = 0; k < DH; k++) s += Win[i * DH + k] * sW1[k * DH + j];
    g_Wc[o] = s;
    if (o < DH) {
        float b = 0.f;
#pragma unroll 16
        for (int k = 0; k < DH; k++) b += b_in[k] * sW1[k * DH + j];
        g_bc[o] = b;
    }
}

// ---------------- small utility kernels ----------------
__global__ void zero_kernel(int n) {
    int i = blockIdx.x * blockDim.x + threadIdx.x;
    if (i < n) { g_degi[i] = 0; g_cur[i] = 0; }
    if (i < DH) {
        g_sum1[i] = 0.0; g_sq1[i] = 0.0;
        g_sum2[i] = 0.0; g_sq2[i] = 0.0;
    }
}

__global__ void deg_kernel(const int* __restrict__ dst, int E) {
    int e = blockIdx.x * blockDim.x + threadIdx.x;
    if (e < E) atomicAdd(&g_degi[dst[e]], 1);
}

// block-level inclusive scan -> exclusive offsets + block sums (+ dinv fused)
__global__ void __launch_bounds__(1024) scan1_kernel(int n) {
    __shared__ int s[1024];
    int t = threadIdx.x;
    int i = blockIdx.x * 1024 + t;
    int v = (i < n) ? g_degi[i] : 0;
    s[t] = v; __syncthreads();
#pragma unroll
    for (int off = 1; off < 1024; off <<= 1) {
        int tmp = (t >= off) ? s[t - off] : 0;
        __syncthreads();
        s[t] += tmp;
        __syncthreads();
    }
    if (i < n) {
        g_off[i] = s[t] - v;
        g_dinv[i] = rsqrtf((float)v + 1.0f);
    }
    if (t == 1023) g_bsum[blockIdx.x] = s[1023];
}

__global__ void __launch_bounds__(256) scan2_kernel(int nb) {
    __shared__ int s[256];
    int t = threadIdx.x;
    int v = (t < nb) ? g_bsum[t] : 0;
    s[t] = v; __syncthreads();
#pragma unroll
    for (int off = 1; off < 256; off <<= 1) {
        int tmp = (t >= off) ? s[t - off] : 0;
        __syncthreads();
        s[t] += tmp;
        __syncthreads();
    }
    if (t < nb) g_bsum[t] = s[t] - v;
}

__global__ void __launch_bounds__(256) fill_kernel(const int* __restrict__ src,
                                                   const int* __restrict__ dst, int E) {
    int e = blockIdx.x * blockDim.x + threadIdx.x;
    if (e >= E) return;
    int d = dst[e], s = src[e];
    int p = g_off[d] + g_bsum[d >> 10] + atomicAdd(&g_cur[d], 1);
    g_ssrc[p] = s;
    g_scoef[p] = g_dinv[s] * g_dinv[d];
}

// ---------------- GEMM: g_xw[n,64] = X[n,K] @ W[K,64] (+ bias for MODE 0) ----------------
// MODE 0: X = external input, W = g_Wc, bias = g_bc (proj+layer1 folded)
// MODE 2: X = norm(g_agg)+leaky (GraphNorm folded A,B)
// 256 threads, 128 rows/block, per-thread 4 rows x 8 cols via FFMA2.
template<int K, int MODE>
__global__ void __launch_bounds__(256)
gemm_kernel(const float* __restrict__ Xext, const float* __restrict__ W, int n) {
    constexpr int S = K + 2;          // pad: 4*S % 32 == 8 -> conflict-free rg banks
    constexpr int BR = 128;
    constexpr int KQ = K / 4;
    extern __shared__ float sm[];
    float* sW = sm;                   // K*64
    float* sX = sm + K * DH;          // BR*S

    const int tid = threadIdx.x;
    const int row0 = blockIdx.x * BR;
    const float* X = (MODE == 0) ? Xext : g_agg;
    const float* Wsrc = (MODE == 0) ? g_Wc : W;

    for (int i = tid * 4; i < K * DH; i += 1024)
        *(float4*)(sW + i) = *(const float4*)(Wsrc + i);

    for (int i = tid; i < BR * KQ; i += 256) {
        int r = i / KQ, kq = (i - r * KQ) * 4;
        int gr = row0 + r;
        float4 v = make_float4(0.f, 0.f, 0.f, 0.f);
        if (gr < n) {
            v = *(const float4*)(X + (size_t)gr * K + kq);
            if (MODE == 2) {
                float4 A = *(const float4*)&g_A[kq];
                float4 B = *(const float4*)&g_B[kq];
                v.x = A.x * v.x + B.x;
                v.y = A.y * v.y + B.y;
                v.z = A.z * v.z + B.z;
                v.w = A.w * v.w + B.w;
                v.x = v.x > 0.f ? v.x : SLOPE * v.x;
                v.y = v.y > 0.f ? v.y : SLOPE * v.y;
                v.z = v.z > 0.f ? v.z : SLOPE * v.z;
                v.w = v.w > 0.f ? v.w : SLOPE * v.w;
            }
        }
        float* p = sX + r * S + kq;
        p[0] = v.x; p[1] = v.y; p[2] = v.z; p[3] = v.w;
    }
    __syncthreads();

    const int cg = tid & 7, rg = tid >> 3;
    const int c0 = cg * 8, r0 = rg * 4;
    ull acc[4][4];
#pragma unroll
    for (int i = 0; i < 4; i++)
#pragma unroll
        for (int j = 0; j < 4; j++) acc[i][j] = 0ull;

    const float* xp = sX + r0 * S;
    const float* wp = sW + c0;

#pragma unroll 4
    for (int k = 0; k < K; k++) {
        ull X0, X1, X2, X3;
        PACK2(X0, xp[k]);
        PACK2(X1, xp[S + k]);
        PACK2(X2, xp[2 * S + k]);
        PACK2(X3, xp[3 * S + k]);
        ulonglong2 wa = *(const ulonglong2*)(wp + (size_t)k * DH);
        ulonglong2 wb = *(const ulonglong2*)(wp + (size_t)k * DH + 4);
        FMA2(acc[0][0], X0, wa.x); FMA2(acc[0][1], X0, wa.y);
        FMA2(acc[0][2], X0, wb.x); FMA2(acc[0][3], X0, wb.y);
        FMA2(acc[1][0], X1, wa.x); FMA2(acc[1][1], X1, wa.y);
        FMA2(acc[1][2], X1, wb.x); FMA2(acc[1][3], X1, wb.y);
        FMA2(acc[2][0], X2, wa.x); FMA2(acc[2][1], X2, wa.y);
        FMA2(acc[2][2], X2, wb.x); FMA2(acc[2][3], X2, wb.y);
        FMA2(acc[3][0], X3, wa.x); FMA2(acc[3][1], X3, wa.y);
        FMA2(acc[3][2], X3, wb.x); FMA2(acc[3][3], X3, wb.y);
    }

    if (MODE == 0) {
        ulonglong2 ba = *(const ulonglong2*)(g_bc + c0);
        ulonglong2 bb = *(const ulonglong2*)(g_bc + c0 + 4);
#pragma unroll
        for (int i = 0; i < 4; i++) {
            int gr = row0 + r0 + i;
            if (gr < n) {
                ull o0, o1, o2, o3;
                ADD2(o0, acc[i][0], ba.x); ADD2(o1, acc[i][1], ba.y);
                ADD2(o2, acc[i][2], bb.x); ADD2(o3, acc[i][3], bb.y);
                ulonglong2* dp = (ulonglong2*)&g_xw[(size_t)gr * DH + c0];
                dp[0] = make_ulonglong2(o0, o1);
                dp[1] = make_ulonglong2(o2, o3);
            }
        }
    } else {
#pragma unroll
        for (int i = 0; i < 4; i++) {
            int gr = row0 + r0 + i;
            if (gr < n) {
                ulonglong2* dp = (ulonglong2*)&g_xw[(size_t)gr * DH + c0];
                dp[0] = make_ulonglong2(acc[i][0], acc[i][1]);
                dp[1] = make_ulonglong2(acc[i][2], acc[i][3]);
            }
        }
    }
}

// ---------------- CSR gather aggregation: one warp per node ----------------
// agg[i] = sum_{e in in(i)} coef[e]*xw[src[e]] + dinv[i]^2*xw[i] + bias
__global__ void __launch_bounds__(256)
agg_kernel(const float* __restrict__ bias, int n) {
    int w = (blockIdx.x * 256 + threadIdx.x) >> 5;
    if (w >= n) return;
    int lane = threadIdx.x & 31;
    int half = lane >> 4;
    int q = (lane & 15) << 2;
    int start = g_off[w] + g_bsum[w >> 10];
    int end = start + g_degi[w];

    float4 a = make_float4(0.f, 0.f, 0.f, 0.f);
    float4 b = make_float4(0.f, 0.f, 0.f, 0.f);
    int e = start + half;
    // 2 independent in-flight gathers per half-warp for MLP
    for (; e + 2 < end; e += 4) {
        int s0 = g_ssrc[e];     float c0 = g_scoef[e];
        int s1 = g_ssrc[e + 2]; float c1 = g_scoef[e + 2];
        float4 v0 = *(const float4*)&g_xw[(size_t)s0 * DH + q];
        float4 v1 = *(const float4*)&g_xw[(size_t)s1 * DH + q];
        a.x += c0 * v0.x; a.y += c0 * v0.y; a.z += c0 * v0.z; a.w += c0 * v0.w;
        b.x += c1 * v1.x; b.y += c1 * v1.y; b.z += c1 * v1.z; b.w += c1 * v1.w;
    }
    if (e < end) {
        int s0 = g_ssrc[e]; float c0 = g_scoef[e];
        float4 v0 = *(const float4*)&g_xw[(size_t)s0 * DH + q];
        a.x += c0 * v0.x; a.y += c0 * v0.y; a.z += c0 * v0.z; a.w += c0 * v0.w;
    }
    a.x += b.x; a.y += b.y; a.z += b.z; a.w += b.w;

    a.x += __shfl_xor_sync(0xffffffffu, a.x, 16);
    a.y += __shfl_xor_sync(0xffffffffu, a.y, 16);
    a.z += __shfl_xor_sync(0xffffffffu, a.z, 16);
    a.w += __shfl_xor_sync(0xffffffffu, a.w, 16);
    if (half == 0) {
        float d = g_dinv[w];
        float d2 = d * d;
        float4 xv = *(const float4*)&g_xw[(size_t)w * DH + q];
        float4 bb = *(const float4*)&bias[q];
        float4 o;
        o.x = a.x + d2 * xv.x + bb.x;
        o.y = a.y + d2 * xv.y + bb.y;
        o.z = a.z + d2 * xv.z + bb.z;
        o.w = a.w + d2 * xv.w + bb.w;
        *(float4*)&g_agg[(size_t)w * DH + q] = o;
    }
}

// ---------------- per-feature sum / sumsq reduction over nodes ----------------
template<int L>
__global__ void __launch_bounds__(256)
stats_kernel(int n) {
    int j = threadIdx.x & 63;
    int slot = threadIdx.x >> 6;
    int r = blockIdx.x * 4 + slot;
    int stride = gridDim.x * 4;
    float s = 0.f, q = 0.f;
    for (; r < n; r += stride) {
        float v = g_agg[(size_t)r * DH + j];
        s += v;
        q += v * v;
    }
    __shared__ float ss[4][DH];
    __shared__ float sq[4][DH];
    ss[slot][j] = s;
    sq[slot][j] = q;
    __syncthreads();
    if (threadIdx.x < DH) {
        double S = (double)ss[0][j] + ss[1][j] + ss[2][j] + ss[3][j];
        double Q = (double)sq[0][j] + sq[1][j] + sq[2][j] + sq[3][j];
        if (L == 1) { atomicAdd(&g_sum1[j], S); atomicAdd(&g_sq1[j], Q); }
        else        { atomicAdd(&g_sum2[j], S); atomicAdd(&g_sq2[j], Q); }
    }
}

template<int L>
__global__ void finalize_kernel(const float* __restrict__ alpha,
                                const float* __restrict__ gamma,
                                const float* __restrict__ beta, int n) {
    int j = threadIdx.x;
    if (j >= DH) return;
    double S = (L == 1) ? g_sum1[j] : g_sum2[j];
    double Q = (L == 1) ? g_sq1[j] : g_sq2[j];
    double m = S / (double)n;
    double a = (double)alpha[j];
    double var = Q / (double)n - 2.0 * a * m * m + a * a * m * m;
    float inv = rsqrtf((float)var + EPSN);
    float g = gamma[j] * inv;
    g_A[j] = g;
    g_B[j] = beta[j] - g * (float)(a * m);
}

// final output: out = A*agg + B
__global__ void __launch_bounds__(256)
norm_out_kernel(float* __restrict__ out, int total) {
    int i = blockIdx.x * 256 + threadIdx.x;
    if (i >= total) return;
    int j = i & 63;
    out[i] = g_A[j] * g_agg[i] + g_B[j];
}

// ---------------- launcher ----------------
extern "C" void kernel_launch(void* const* d_in, const int* in_sizes, int n_in,
                              void* d_out, int out_size) {
    const float* x    = (const float*)d_in[0];
    const int*   ei   = (const int*)d_in[1];
    const float* W_in = (const float*)d_in[2];
    const float* b_in = (const float*)d_in[3];
    const float* W1   = (const float*)d_in[4];
    const float* b1   = (const float*)d_in[5];
    const float* a1   = (const float*)d_in[6];
    const float* gm1  = (const float*)d_in[7];
    const float* be1  = (const float*)d_in[8];
    const float* W2   = (const float*)d_in[9];
    const float* b2   = (const float*)d_in[10];
    const float* a2   = (const float*)d_in[11];
    const float* gm2  = (const float*)d_in[12];
    const float* be2  = (const float*)d_in[13];
    float* out = (float*)d_out;

    const int n = in_sizes[0] / DIN;
    const int E = in_sizes[1] / 2;
    const int* src = ei;
    const int* dst = ei + E;
    const int total = n * DH;
    const int nb = (n + 1023) >> 10;

    const int smemP = (DIN * DH + 128 * (DIN + 2)) * 4;  // 99328
    const int smemL = (DH * DH + 128 * (DH + 2)) * 4;    // 50176
    cudaFuncSetAttribute(gemm_kernel<DIN, 0>, cudaFuncAttributeMaxDynamicSharedMemorySize, smemP);
    cudaFuncSetAttribute(gemm_kernel<DH, 2>,  cudaFuncAttributeMaxDynamicSharedMemorySize, smemL);

    const int gemm_blocks = (n + 127) / 128;

    // combined proj+layer1 weight (independent of graph)
    wc_kernel<<<32, 256>>>(W_in, W1, b_in);

    // graph preprocessing (shared by both layers)
    zero_kernel<<<(n + 255) / 256, 256>>>(n);
    deg_kernel<<<(E + 255) / 256, 256>>>(dst, E);
    scan1_kernel<<<nb, 1024>>>(n);
    scan2_kernel<<<1, 256>>>(nb);
    fill_kernel<<<(E + 255) / 256, 256>>>(src, dst, E);

    // ---- layer 1 (proj folded): g_xw = x @ Wc + bc ----
    gemm_kernel<DIN, 0><<<gemm_blocks, 256, smemP>>>(x, nullptr, n);
    agg_kernel<<<(n + 7) / 8, 256>>>(b1, n);
    stats_kernel<1><<<1184, 256>>>(n);
    finalize_kernel<1><<<1, 64>>>(a1, gm1, be1, n);

    // ---- layer 2 (GraphNorm1 + LeakyReLU fused into gemm input load) ----
    gemm_kernel<DH, 2><<<gemm_blocks, 256, smemL>>>(nullptr, W2, n);
    agg_kernel<<<(n + 7) / 8, 256>>>(b2, n);
    stats_kernel<2><<<1184, 256>>>(n);
    finalize_kernel<2><<<1, 64>>>(a2, gm2, be2, n);
    norm_out_kernel<<<(total + 255) / 256, 256>>>(out, total);
}